// round 13
// baseline (speedup 1.0000x reference)
#include <cuda_runtime.h>
#include <math.h>

// Problem constants
#define B_ 8
#define N_ 4096
#define S_ 512
#define D_ 512
#define H_ 8
#define HD_ 64

// Scratch (allocation-free rule: __device__ globals)
__device__ float g_Q[(size_t)B_ * N_ * D_];
__device__ float g_KV[(size_t)B_ * S_ * 2 * D_];
__device__ float g_O[(size_t)B_ * N_ * D_];

// ---------------------------------------------------------------------------
// tf32 helpers
// ---------------------------------------------------------------------------
__device__ __forceinline__ unsigned f2tf(float x) {
    unsigned r;
    asm("cvt.rna.tf32.f32 %0, %1;" : "=r"(r) : "f"(x));
    return r;
}

__device__ __forceinline__ void mma_tf32(float* d, const unsigned* a, const unsigned* b) {
    asm volatile(
        "mma.sync.aligned.m16n8k8.row.col.f32.tf32.tf32.f32 "
        "{%0,%1,%2,%3}, {%4,%5,%6,%7}, {%8,%9}, {%0,%1,%2,%3};\n"
        : "+f"(d[0]), "+f"(d[1]), "+f"(d[2]), "+f"(d[3])
        : "r"(a[0]), "r"(a[1]), "r"(a[2]), "r"(a[3]), "r"(b[0]), "r"(b[1]));
}

// ---------------------------------------------------------------------------
// GEMM: C[m][n] = sum_k A[m][k] * W[n][k] + bias[n]   (tf32 mma.sync)
// BM=BN=128, BK=32. 128 threads = 4 warps (2m x 2n), warp tile 64x64.
// Per ks-step: 32 LDS feed 32 MMAs (LDS:MMA = 1.0). 2 CTAs/SM.
// ---------------------------------------------------------------------------
#define GPAD 36
#define GTILE (128 * GPAD)

template <int KD>
__global__ __launch_bounds__(128, 2) void gemm_tf32(
    const float* __restrict__ A, const float* __restrict__ W,
    const float* __restrict__ bias, float* __restrict__ C,
    int M, int Nd)
{
    extern __shared__ unsigned sg[];
    unsigned* As = sg;                // [2][128][36]
    unsigned* Ws = sg + 2 * GTILE;    // [2][128][36]

    const int tid = threadIdx.x;
    const int lane = tid & 31;
    const int warp = tid >> 5;
    const int wm = warp >> 1;         // 0..1
    const int wn = warp & 1;          // 0..1
    const int m0 = blockIdx.y * 128;
    const int n0 = blockIdx.x * 128;

    float acc[4][8][4];
#pragma unroll
    for (int i = 0; i < 4; i++)
#pragma unroll
        for (int j = 0; j < 8; j++)
#pragma unroll
            for (int r = 0; r < 4; r++) acc[i][j][r] = 0.f;

    float4 pa[8], pw[8];
    constexpr int nkt = KD / 32;

    // prefetch tile 0: A 128x32 = 1024 float4 over 128 threads -> 8 each
#pragma unroll
    for (int l = 0; l < 8; l++) {
        int idx = tid + l * 128;
        int row = idx >> 3;
        int c4 = (idx & 7) * 4;
        pa[l] = *(const float4*)(A + (size_t)(m0 + row) * KD + c4);
        pw[l] = *(const float4*)(W + (size_t)(n0 + row) * KD + c4);
    }
#pragma unroll
    for (int l = 0; l < 8; l++) {
        int idx = tid + l * 128;
        int row = idx >> 3;
        int c4 = (idx & 7) * 4;
        uint4 ua = make_uint4(f2tf(pa[l].x), f2tf(pa[l].y), f2tf(pa[l].z), f2tf(pa[l].w));
        uint4 uw = make_uint4(f2tf(pw[l].x), f2tf(pw[l].y), f2tf(pw[l].z), f2tf(pw[l].w));
        *(uint4*)(As + row * GPAD + c4) = ua;
        *(uint4*)(Ws + row * GPAD + c4) = uw;
    }
    __syncthreads();

#pragma unroll 2
    for (int kt = 0; kt < nkt; kt++) {
        if (kt + 1 < nkt) {
#pragma unroll
            for (int l = 0; l < 8; l++) {
                int idx = tid + l * 128;
                int row = idx >> 3;
                int c4 = (idx & 7) * 4;
                pa[l] = *(const float4*)(A + (size_t)(m0 + row) * KD + (kt + 1) * 32 + c4);
                pw[l] = *(const float4*)(W + (size_t)(n0 + row) * KD + (kt + 1) * 32 + c4);
            }
        }
        const unsigned* Ab = As + (kt & 1) * GTILE + (wm * 64) * GPAD;
        const unsigned* Wb = Ws + (kt & 1) * GTILE + (wn * 64) * GPAD;

#pragma unroll
        for (int ks = 0; ks < 32; ks += 8) {
            unsigned af[4][4], bf[8][2];
#pragma unroll
            for (int mt = 0; mt < 4; mt++) {
                const unsigned* p = Ab + (mt * 16 + (lane >> 2)) * GPAD + ks + (lane & 3);
                af[mt][0] = p[0];
                af[mt][1] = p[8 * GPAD];
                af[mt][2] = p[4];
                af[mt][3] = p[8 * GPAD + 4];
            }
#pragma unroll
            for (int nt = 0; nt < 8; nt++) {
                const unsigned* p = Wb + (nt * 8 + (lane >> 2)) * GPAD + ks + (lane & 3);
                bf[nt][0] = p[0];
                bf[nt][1] = p[4];
            }
#pragma unroll
            for (int mt = 0; mt < 4; mt++)
#pragma unroll
                for (int nt = 0; nt < 8; nt++)
                    mma_tf32(acc[mt][nt], af[mt], bf[nt]);
        }
        // Store next tile into the OTHER buffer (its readers finished before
        // the previous barrier), then one barrier.
        if (kt + 1 < nkt) {
            unsigned* Ad = As + ((kt + 1) & 1) * GTILE;
            unsigned* Wd = Ws + ((kt + 1) & 1) * GTILE;
#pragma unroll
            for (int l = 0; l < 8; l++) {
                int idx = tid + l * 128;
                int row = idx >> 3;
                int c4 = (idx & 7) * 4;
                uint4 ua = make_uint4(f2tf(pa[l].x), f2tf(pa[l].y), f2tf(pa[l].z), f2tf(pa[l].w));
                uint4 uw = make_uint4(f2tf(pw[l].x), f2tf(pw[l].y), f2tf(pw[l].z), f2tf(pw[l].w));
                *(uint4*)(Ad + row * GPAD + c4) = ua;
                *(uint4*)(Wd + row * GPAD + c4) = uw;
            }
            __syncthreads();
        }
    }

    // epilogue + bias
#pragma unroll
    for (int mt = 0; mt < 4; mt++) {
        int row0 = m0 + wm * 64 + mt * 16 + (lane >> 2);
#pragma unroll
        for (int nt = 0; nt < 8; nt++) {
            int col = n0 + wn * 64 + nt * 8 + (lane & 3) * 2;
            float2 bb = *(const float2*)(bias + col);
            float2 v0, v1;
            v0.x = acc[mt][nt][0] + bb.x;
            v0.y = acc[mt][nt][1] + bb.y;
            v1.x = acc[mt][nt][2] + bb.x;
            v1.y = acc[mt][nt][3] + bb.y;
            *(float2*)(C + (size_t)row0 * Nd + col) = v0;
            *(float2*)(C + (size_t)(row0 + 8) * Nd + col) = v1;
        }
    }
}

// ---------------------------------------------------------------------------
// Flash attention, tf32 tensor cores (UNCHANGED from R10 passing kernel).
// CTA = 256 queries of one (b,h). 256 threads; warp owns 32 q-rows. S-tiles 64.
// ---------------------------------------------------------------------------
#define APAD 68
#define QT 256
#define OFF_QS 0
#define OFF_KS (QT * APAD)
#define OFF_PS (QT * APAD + 64 * APAD)
#define OFF_VS (2 * QT * APAD + 64 * APAD)
#define OFF_MA (2 * QT * APAD + 64 * APAD + 64 * 64)
#define ATTN_SMEM_U32 (2 * QT * APAD + 64 * APAD + 64 * 64 + 512)

__device__ __forceinline__ int vswz(int d, int s) {
    return d * 64 + ((s + 4 * d + (d >> 3)) & 63);
}

__global__ __launch_bounds__(256, 1) void attn_tf32(
    const float* __restrict__ Q, const float* __restrict__ KV,
    const int* __restrict__ mask, float* __restrict__ O)
{
    extern __shared__ unsigned sa[];
    unsigned* Qs = sa + OFF_QS;
    unsigned* Ks = sa + OFF_KS;
    unsigned* Ps = sa + OFF_PS;
    unsigned* Vs = sa + OFF_VS;
    float* mAdd = (float*)(sa + OFF_MA);

    const int tid = threadIdx.x;
    const int lane = tid & 31;
    const int warp = tid >> 5;
    const int n0 = blockIdx.x * QT;
    const int h = blockIdx.y;
    const int b = blockIdx.z;

    const float* Qb = Q + ((size_t)b * N_ + n0) * D_ + h * HD_;
    const float* Kb = KV + (size_t)b * S_ * (2 * D_) + h * HD_;
    const float* Vb = Kb + D_;
    const int* mb = mask + b * S_;
    float* Ob = O + ((size_t)b * N_ + n0) * D_ + h * HD_;

#pragma unroll
    for (int l = 0; l < 16; l++) {
        int idx = tid + l * 256;
        int q = idx >> 4;
        int d4 = (idx & 15) * 4;
        float4 v = *(const float4*)(Qb + (size_t)q * D_ + d4);
        uint4 u = make_uint4(f2tf(v.x * 0.125f), f2tf(v.y * 0.125f),
                             f2tf(v.z * 0.125f), f2tf(v.w * 0.125f));
        *(uint4*)(Qs + q * APAD + d4) = u;
    }
    for (int s = tid; s < S_; s += 256) mAdd[s] = mb[s] ? -1e5f : 0.f;

    float o[2][8][4];
#pragma unroll
    for (int mt = 0; mt < 2; mt++)
#pragma unroll
        for (int i = 0; i < 8; i++)
#pragma unroll
            for (int r = 0; r < 4; r++) o[mt][i][r] = 0.f;
    float mrow[2][2], lrow[2][2];
#pragma unroll
    for (int mt = 0; mt < 2; mt++) {
        mrow[mt][0] = -1e30f; mrow[mt][1] = -1e30f;
        lrow[mt][0] = 0.f;    lrow[mt][1] = 0.f;
    }

    const int q0 = warp * 32 + (lane >> 2);

    __syncthreads();

    for (int st = 0; st < S_; st += 64) {
#pragma unroll
        for (int l = 0; l < 4; l++) {
            int idx = tid + l * 256;
            int s = idx >> 4;
            int d4 = (idx & 15) * 4;
            float4 vk = *(const float4*)(Kb + (size_t)(st + s) * (2 * D_) + d4);
            uint4 uk = make_uint4(f2tf(vk.x), f2tf(vk.y), f2tf(vk.z), f2tf(vk.w));
            *(uint4*)(Ks + s * APAD + d4) = uk;
            float4 vv = *(const float4*)(Vb + (size_t)(st + s) * (2 * D_) + d4);
            Vs[vswz(d4 + 0, s)] = f2tf(vv.x);
            Vs[vswz(d4 + 1, s)] = f2tf(vv.y);
            Vs[vswz(d4 + 2, s)] = f2tf(vv.z);
            Vs[vswz(d4 + 3, s)] = f2tf(vv.w);
        }
        __syncthreads();

        float sc[2][8][4];
#pragma unroll
        for (int mt = 0; mt < 2; mt++)
#pragma unroll
            for (int nt = 0; nt < 8; nt++)
#pragma unroll
                for (int r = 0; r < 4; r++) sc[mt][nt][r] = 0.f;

#pragma unroll
        for (int ks = 0; ks < 64; ks += 8) {
            unsigned af[2][4];
#pragma unroll
            for (int mt = 0; mt < 2; mt++) {
                const unsigned* pq = Qs + (q0 + mt * 16) * APAD + ks + (lane & 3);
                af[mt][0] = pq[0];
                af[mt][1] = pq[8 * APAD];
                af[mt][2] = pq[4];
                af[mt][3] = pq[8 * APAD + 4];
            }
#pragma unroll
            for (int nt = 0; nt < 8; nt++) {
                unsigned bf[2];
                const unsigned* pk = Ks + (nt * 8 + (lane >> 2)) * APAD + ks + (lane & 3);
                bf[0] = pk[0];
                bf[1] = pk[4];
                mma_tf32(sc[0][nt], af[0], bf);
                mma_tf32(sc[1][nt], af[1], bf);
            }
        }

#pragma unroll
        for (int mt = 0; mt < 2; mt++) {
            float rm0 = -1e30f, rm1 = -1e30f;
#pragma unroll
            for (int nt = 0; nt < 8; nt++) {
                int col = st + nt * 8 + (lane & 3) * 2;
                float a0 = mAdd[col], a1 = mAdd[col + 1];
                sc[mt][nt][0] += a0; sc[mt][nt][1] += a1;
                sc[mt][nt][2] += a0; sc[mt][nt][3] += a1;
                rm0 = fmaxf(rm0, fmaxf(sc[mt][nt][0], sc[mt][nt][1]));
                rm1 = fmaxf(rm1, fmaxf(sc[mt][nt][2], sc[mt][nt][3]));
            }
            rm0 = fmaxf(rm0, __shfl_xor_sync(0xffffffffu, rm0, 1));
            rm0 = fmaxf(rm0, __shfl_xor_sync(0xffffffffu, rm0, 2));
            rm1 = fmaxf(rm1, __shfl_xor_sync(0xffffffffu, rm1, 1));
            rm1 = fmaxf(rm1, __shfl_xor_sync(0xffffffffu, rm1, 2));

            float mn0 = fmaxf(mrow[mt][0], rm0), mn1 = fmaxf(mrow[mt][1], rm1);
            float c0 = __expf(mrow[mt][0] - mn0), c1 = __expf(mrow[mt][1] - mn1);
            float rs0 = 0.f, rs1 = 0.f;
#pragma unroll
            for (int nt = 0; nt < 8; nt++) {
                sc[mt][nt][0] = __expf(sc[mt][nt][0] - mn0);
                sc[mt][nt][1] = __expf(sc[mt][nt][1] - mn0);
                sc[mt][nt][2] = __expf(sc[mt][nt][2] - mn1);
                sc[mt][nt][3] = __expf(sc[mt][nt][3] - mn1);
                rs0 += sc[mt][nt][0] + sc[mt][nt][1];
                rs1 += sc[mt][nt][2] + sc[mt][nt][3];
            }
            rs0 += __shfl_xor_sync(0xffffffffu, rs0, 1);
            rs0 += __shfl_xor_sync(0xffffffffu, rs0, 2);
            rs1 += __shfl_xor_sync(0xffffffffu, rs1, 1);
            rs1 += __shfl_xor_sync(0xffffffffu, rs1, 2);

            lrow[mt][0] = lrow[mt][0] * c0 + rs0;
            lrow[mt][1] = lrow[mt][1] * c1 + rs1;
            mrow[mt][0] = mn0;
            mrow[mt][1] = mn1;

#pragma unroll
            for (int dt = 0; dt < 8; dt++) {
                o[mt][dt][0] *= c0; o[mt][dt][1] *= c0;
                o[mt][dt][2] *= c1; o[mt][dt][3] *= c1;
            }

#pragma unroll
            for (int nt = 0; nt < 8; nt++) {
                int col = nt * 8 + (lane & 3) * 2;
                *(uint2*)(Ps + (q0 + mt * 16) * APAD + col) =
                    make_uint2(f2tf(sc[mt][nt][0]), f2tf(sc[mt][nt][1]));
                *(uint2*)(Ps + (q0 + mt * 16 + 8) * APAD + col) =
                    make_uint2(f2tf(sc[mt][nt][2]), f2tf(sc[mt][nt][3]));
            }
        }
        __syncwarp();

#pragma unroll
        for (int ss = 0; ss < 64; ss += 8) {
            unsigned af[2][4];
#pragma unroll
            for (int mt = 0; mt < 2; mt++) {
                const unsigned* pp = Ps + (q0 + mt * 16) * APAD + ss + (lane & 3);
                af[mt][0] = pp[0];
                af[mt][1] = pp[8 * APAD];
                af[mt][2] = pp[4];
                af[mt][3] = pp[8 * APAD + 4];
            }
#pragma unroll
            for (int dt = 0; dt < 8; dt++) {
                int d = dt * 8 + (lane >> 2);
                unsigned bf[2];
                bf[0] = Vs[vswz(d, ss + (lane & 3))];
                bf[1] = Vs[vswz(d, ss + 4 + (lane & 3))];
                mma_tf32(o[0][dt], af[0], bf);
                mma_tf32(o[1][dt], af[1], bf);
            }
        }
        __syncthreads();
    }

#pragma unroll
    for (int mt = 0; mt < 2; mt++) {
        float inv0 = 1.0f / lrow[mt][0], inv1 = 1.0f / lrow[mt][1];
#pragma unroll
        for (int dt = 0; dt < 8; dt++) {
            int col = dt * 8 + (lane & 3) * 2;
            float2 v0, v1;
            v0.x = o[mt][dt][0] * inv0; v0.y = o[mt][dt][1] * inv0;
            v1.x = o[mt][dt][2] * inv1; v1.y = o[mt][dt][3] * inv1;
            *(float2*)(Ob + (size_t)(q0 + mt * 16) * D_ + col) = v0;
            *(float2*)(Ob + (size_t)(q0 + mt * 16 + 8) * D_ + col) = v1;
        }
    }
}

// ---------------------------------------------------------------------------
// Launch. Inputs: x, context, context_mask(int32), wq, bq, wkv, bkv, wp, bp
// ---------------------------------------------------------------------------
extern "C" void kernel_launch(void* const* d_in, const int* in_sizes, int n_in,
                              void* d_out, int out_size)
{
    const float* x = (const float*)d_in[0];
    const float* ctx = (const float*)d_in[1];
    const int* mask = (const int*)d_in[2];
    const float* wq = (const float*)d_in[3];
    const float* bq = (const float*)d_in[4];
    const float* wkv = (const float*)d_in[5];
    const float* bkv = (const float*)d_in[6];
    const float* wp = (const float*)d_in[7];
    const float* bp = (const float*)d_in[8];
    float* out = (float*)d_out;

    float *Qp, *KVp, *Op;
    cudaGetSymbolAddress((void**)&Qp, g_Q);
    cudaGetSymbolAddress((void**)&KVp, g_KV);
    cudaGetSymbolAddress((void**)&Op, g_O);

    int gemm_smem = 4 * GTILE * (int)sizeof(unsigned);      // 73728
    int attn_smem = ATTN_SMEM_U32 * (int)sizeof(unsigned);  // ~175KB

    cudaFuncSetAttribute((const void*)gemm_tf32<512>,
                         cudaFuncAttributeMaxDynamicSharedMemorySize, gemm_smem);
    cudaFuncSetAttribute((const void*)attn_tf32,
                         cudaFuncAttributeMaxDynamicSharedMemorySize, attn_smem);

    // Q projection: [B*N, D] x [D, D]^T
    gemm_tf32<512><<<dim3(D_ / 128, (B_ * N_) / 128), 128, gemm_smem>>>(x, wq, bq, Qp, B_ * N_, D_);
    // KV projection: [B*S, D] x [2D, D]^T
    gemm_tf32<512><<<dim3((2 * D_) / 128, (B_ * S_) / 128), 128, gemm_smem>>>(ctx, wkv, bkv, KVp, B_ * S_, 2 * D_);
    // attention
    attn_tf32<<<dim3(N_ / QT, H_, B_), 256, attn_smem>>>(Qp, KVp, mask, Op);
    // output projection
    gemm_tf32<512><<<dim3(D_ / 128, (B_ * N_) / 128), 128, gemm_smem>>>(Op, wp, bp, out, B_ * N_, D_);
}

// round 15
// speedup vs baseline: 1.6356x; 1.6356x over previous
#include <cuda_runtime.h>
#include <cuda_fp16.h>
#include <cstdint>
#include <math.h>

// Problem constants
#define B_ 8
#define N_ 4096
#define S_ 512
#define D_ 512
#define H_ 8
#define HD_ 64

// Scratch (allocation-free rule: __device__ globals)
__device__ float g_Q[(size_t)B_ * N_ * D_];
__device__ float g_KV[(size_t)B_ * S_ * 2 * D_];
__device__ float g_O[(size_t)B_ * N_ * D_];

// ---------------------------------------------------------------------------
// fp16 mma helpers (m16n8k16, fp32 accumulate)
// ---------------------------------------------------------------------------
__device__ __forceinline__ void mma_fp16(float* d, const unsigned* a, const unsigned* b) {
    asm volatile(
        "mma.sync.aligned.m16n8k16.row.col.f32.f16.f16.f32 "
        "{%0,%1,%2,%3}, {%4,%5,%6,%7}, {%8,%9}, {%0,%1,%2,%3};\n"
        : "+f"(d[0]), "+f"(d[1]), "+f"(d[2]), "+f"(d[3])
        : "r"(a[0]), "r"(a[1]), "r"(a[2]), "r"(a[3]), "r"(b[0]), "r"(b[1]));
}

__device__ __forceinline__ unsigned h2u(__half2 h) {
    return *(unsigned*)&h;
}

__device__ __forceinline__ unsigned smem_u32(const void* p) {
    unsigned a;
    asm("{ .reg .u64 t; cvta.to.shared.u64 t, %1; cvt.u32.u64 %0, t; }"
        : "=r"(a) : "l"(p));
    return a;
}

// ---------------------------------------------------------------------------
// GEMM: C[m][n] = sum_k A[m][k] * W[n][k] + bias[n]   (fp16 mma, fp32 accum)
// BM=BN=128, BK=32. 256 threads = 8 warps (2m x 4n), warp tile 64x32.
// Rows of 40 halves (32 + 8 pad): conflict-free fragment LDS.
// ---------------------------------------------------------------------------
#define GPADH 40
#define GTILEH (128 * GPADH)

template <int KD>
__global__ __launch_bounds__(256, 2) void gemm_fp16(
    const float* __restrict__ A, const float* __restrict__ W,
    const float* __restrict__ bias, float* __restrict__ C,
    int M, int Nd)
{
    extern __shared__ __half sg[];
    __half* As = sg;                  // [2][128][40]
    __half* Ws = sg + 2 * GTILEH;     // [2][128][40]

    const int tid = threadIdx.x;
    const int lane = tid & 31;
    const int warp = tid >> 5;
    const int wm = warp >> 2;         // 0..1
    const int wn = warp & 3;          // 0..3
    const int m0 = blockIdx.y * 128;
    const int n0 = blockIdx.x * 128;
    const int g = lane >> 2;
    const int c = lane & 3;

    float acc[4][4][4];
#pragma unroll
    for (int i = 0; i < 4; i++)
#pragma unroll
        for (int j = 0; j < 4; j++)
#pragma unroll
            for (int r = 0; r < 4; r++) acc[i][j][r] = 0.f;

    float4 pa[4], pw[4];
    constexpr int nkt = KD / 32;

    // prefetch tile 0: 128 rows x 8 float4 = 1024 over 256 threads -> 4 each
#pragma unroll
    for (int l = 0; l < 4; l++) {
        int idx = tid + l * 256;
        int row = idx >> 3;
        int c4 = (idx & 7) * 4;
        pa[l] = *(const float4*)(A + (size_t)(m0 + row) * KD + c4);
        pw[l] = *(const float4*)(W + (size_t)(n0 + row) * KD + c4);
    }
#pragma unroll
    for (int l = 0; l < 4; l++) {
        int idx = tid + l * 256;
        int row = idx >> 3;
        int c4 = (idx & 7) * 4;
        uint2 ua = make_uint2(h2u(__floats2half2_rn(pa[l].x, pa[l].y)),
                              h2u(__floats2half2_rn(pa[l].z, pa[l].w)));
        uint2 uw = make_uint2(h2u(__floats2half2_rn(pw[l].x, pw[l].y)),
                              h2u(__floats2half2_rn(pw[l].z, pw[l].w)));
        *(uint2*)(As + row * GPADH + c4) = ua;
        *(uint2*)(Ws + row * GPADH + c4) = uw;
    }
    __syncthreads();

#pragma unroll 2
    for (int kt = 0; kt < nkt; kt++) {
        if (kt + 1 < nkt) {
#pragma unroll
            for (int l = 0; l < 4; l++) {
                int idx = tid + l * 256;
                int row = idx >> 3;
                int c4 = (idx & 7) * 4;
                pa[l] = *(const float4*)(A + (size_t)(m0 + row) * KD + (kt + 1) * 32 + c4);
                pw[l] = *(const float4*)(W + (size_t)(n0 + row) * KD + (kt + 1) * 32 + c4);
            }
        }
        const __half* Ab = As + (kt & 1) * GTILEH + (wm * 64) * GPADH;
        const __half* Wb = Ws + (kt & 1) * GTILEH + (wn * 32) * GPADH;

#pragma unroll
        for (int k0 = 0; k0 < 32; k0 += 16) {
            unsigned af[4][4], bf[4][2];
#pragma unroll
            for (int mt = 0; mt < 4; mt++) {
                const __half* p = Ab + (mt * 16 + g) * GPADH + k0 + 2 * c;
                af[mt][0] = *(const unsigned*)p;
                af[mt][1] = *(const unsigned*)(p + 8 * GPADH);
                af[mt][2] = *(const unsigned*)(p + 8);
                af[mt][3] = *(const unsigned*)(p + 8 * GPADH + 8);
            }
#pragma unroll
            for (int nt = 0; nt < 4; nt++) {
                const __half* p = Wb + (nt * 8 + g) * GPADH + k0 + 2 * c;
                bf[nt][0] = *(const unsigned*)p;
                bf[nt][1] = *(const unsigned*)(p + 8);
            }
#pragma unroll
            for (int mt = 0; mt < 4; mt++)
#pragma unroll
                for (int nt = 0; nt < 4; nt++)
                    mma_fp16(acc[mt][nt], af[mt], bf[nt]);
        }
        // Store next tile into the OTHER buffer (readers finished before the
        // previous barrier), then one barrier.
        if (kt + 1 < nkt) {
            __half* Ad = As + ((kt + 1) & 1) * GTILEH;
            __half* Wd = Ws + ((kt + 1) & 1) * GTILEH;
#pragma unroll
            for (int l = 0; l < 4; l++) {
                int idx = tid + l * 256;
                int row = idx >> 3;
                int c4 = (idx & 7) * 4;
                uint2 ua = make_uint2(h2u(__floats2half2_rn(pa[l].x, pa[l].y)),
                                      h2u(__floats2half2_rn(pa[l].z, pa[l].w)));
                uint2 uw = make_uint2(h2u(__floats2half2_rn(pw[l].x, pw[l].y)),
                                      h2u(__floats2half2_rn(pw[l].z, pw[l].w)));
                *(uint2*)(Ad + row * GPADH + c4) = ua;
                *(uint2*)(Wd + row * GPADH + c4) = uw;
            }
            __syncthreads();
        }
    }

    // epilogue + bias (C layout identical to tf32 m16n8k8)
#pragma unroll
    for (int mt = 0; mt < 4; mt++) {
        int row0 = m0 + wm * 64 + mt * 16 + g;
#pragma unroll
        for (int nt = 0; nt < 4; nt++) {
            int col = n0 + wn * 32 + nt * 8 + c * 2;
            float2 bb = *(const float2*)(bias + col);
            float2 v0, v1;
            v0.x = acc[mt][nt][0] + bb.x;
            v0.y = acc[mt][nt][1] + bb.y;
            v1.x = acc[mt][nt][2] + bb.x;
            v1.y = acc[mt][nt][3] + bb.y;
            *(float2*)(C + (size_t)row0 * Nd + col) = v0;
            *(float2*)(C + (size_t)(row0 + 8) * Nd + col) = v1;
        }
    }
}

// ---------------------------------------------------------------------------
// Flash attention, fp16 mma. CTA = 256 queries of one (b,h). 256 threads
// (8 warps); warp owns 32 q-rows (mt=0..1). S-tiles of 64.
// Rows of 72 halves (64 + 8 pad): conflict-free scalar frags + ldmatrix.
// V kept in natural [s][d] layout; B fragments via ldmatrix.x2.trans.
// ---------------------------------------------------------------------------
#define APADH 72
#define QT 256
// half-offsets in dynamic smem
#define QS_H 0
#define KS_H (QT * APADH)
#define PS_H (KS_H + 64 * APADH)
#define VS_H (PS_H + QT * APADH)
#define MA_BYTE ((VS_H + 64 * APADH) * 2)
#define ATTN_SMEM_BYTES (MA_BYTE + 512 * 4)

__global__ __launch_bounds__(256, 1) void attn_fp16(
    const float* __restrict__ Q, const float* __restrict__ KV,
    const int* __restrict__ mask, float* __restrict__ O)
{
    extern __shared__ __half sh[];
    __half* Qs = sh + QS_H;     // [256][72]
    __half* Ks = sh + KS_H;     // [64][72]
    __half* Ps = sh + PS_H;     // [256][72]
    __half* Vs = sh + VS_H;     // [64][72], natural [s][d]
    float* mAdd = (float*)((char*)sh + MA_BYTE);   // [512]

    const int tid = threadIdx.x;
    const int lane = tid & 31;
    const int warp = tid >> 5;
    const int g = lane >> 2;
    const int c = lane & 3;
    const int n0 = blockIdx.x * QT;
    const int h = blockIdx.y;
    const int b = blockIdx.z;

    const float* Qb = Q + ((size_t)b * N_ + n0) * D_ + h * HD_;
    const float* Kb = KV + (size_t)b * S_ * (2 * D_) + h * HD_;
    const float* Vb = Kb + D_;
    const int* mb = mask + b * S_;
    float* Ob = O + ((size_t)b * N_ + n0) * D_ + h * HD_;

    const unsigned vs_base = smem_u32(Vs);

    // load Q tile (pre-scaled by 0.125), cvt to fp16.
    // 256 rows x 16 float4 = 4096 over 256 threads -> 16 iters.
#pragma unroll
    for (int l = 0; l < 16; l++) {
        int idx = tid + l * 256;
        int q = idx >> 4;
        int d4 = (idx & 15) * 4;
        float4 v = *(const float4*)(Qb + (size_t)q * D_ + d4);
        uint2 u = make_uint2(
            h2u(__floats2half2_rn(v.x * 0.125f, v.y * 0.125f)),
            h2u(__floats2half2_rn(v.z * 0.125f, v.w * 0.125f)));
        *(uint2*)(Qs + q * APADH + d4) = u;
    }
    for (int s = tid; s < S_; s += 256) mAdd[s] = mb[s] ? -1e5f : 0.f;

    float o[2][8][4];
#pragma unroll
    for (int mt = 0; mt < 2; mt++)
#pragma unroll
        for (int i = 0; i < 8; i++)
#pragma unroll
            for (int r = 0; r < 4; r++) o[mt][i][r] = 0.f;
    float mrow[2][2], lrow[2][2];
#pragma unroll
    for (int mt = 0; mt < 2; mt++) {
        mrow[mt][0] = -1e30f; mrow[mt][1] = -1e30f;
        lrow[mt][0] = 0.f;    lrow[mt][1] = 0.f;
    }

    const int q0 = warp * 32 + g;   // mt block adds +16

    __syncthreads();

    for (int st = 0; st < S_; st += 64) {
        // load K and V tiles (natural [s][d] layout, fp16):
        // 64 rows x 16 float4 = 1024 over 256 threads -> 4 iters
#pragma unroll
        for (int l = 0; l < 4; l++) {
            int idx = tid + l * 256;
            int s = idx >> 4;
            int d4 = (idx & 15) * 4;
            float4 vk = *(const float4*)(Kb + (size_t)(st + s) * (2 * D_) + d4);
            uint2 uk = make_uint2(h2u(__floats2half2_rn(vk.x, vk.y)),
                                  h2u(__floats2half2_rn(vk.z, vk.w)));
            *(uint2*)(Ks + s * APADH + d4) = uk;
            float4 vv = *(const float4*)(Vb + (size_t)(st + s) * (2 * D_) + d4);
            uint2 uv = make_uint2(h2u(__floats2half2_rn(vv.x, vv.y)),
                                  h2u(__floats2half2_rn(vv.z, vv.w)));
            *(uint2*)(Vs + s * APADH + d4) = uv;
        }
        __syncthreads();

        // QK^T: scores [32q x 64s] per warp, 4 ksteps of k16
        float sc[2][8][4];
#pragma unroll
        for (int mt = 0; mt < 2; mt++)
#pragma unroll
            for (int nt = 0; nt < 8; nt++)
#pragma unroll
                for (int r = 0; r < 4; r++) sc[mt][nt][r] = 0.f;

#pragma unroll
        for (int k0 = 0; k0 < 64; k0 += 16) {
            unsigned af[2][4];
#pragma unroll
            for (int mt = 0; mt < 2; mt++) {
                const __half* pq = Qs + (q0 + mt * 16) * APADH + k0 + 2 * c;
                af[mt][0] = *(const unsigned*)pq;
                af[mt][1] = *(const unsigned*)(pq + 8 * APADH);
                af[mt][2] = *(const unsigned*)(pq + 8);
                af[mt][3] = *(const unsigned*)(pq + 8 * APADH + 8);
            }
#pragma unroll
            for (int nt = 0; nt < 8; nt++) {
                unsigned bf[2];
                const __half* pk = Ks + (nt * 8 + g) * APADH + k0 + 2 * c;
                bf[0] = *(const unsigned*)pk;
                bf[1] = *(const unsigned*)(pk + 8);
                mma_fp16(sc[0][nt], af[0], bf);
                mma_fp16(sc[1][nt], af[1], bf);
            }
        }

        // mask + online softmax, per mt block (rows q0+mt*16, +8)
#pragma unroll
        for (int mt = 0; mt < 2; mt++) {
            float rm0 = -1e30f, rm1 = -1e30f;
#pragma unroll
            for (int nt = 0; nt < 8; nt++) {
                int col = st + nt * 8 + c * 2;
                float a0 = mAdd[col], a1 = mAdd[col + 1];
                sc[mt][nt][0] += a0; sc[mt][nt][1] += a1;
                sc[mt][nt][2] += a0; sc[mt][nt][3] += a1;
                rm0 = fmaxf(rm0, fmaxf(sc[mt][nt][0], sc[mt][nt][1]));
                rm1 = fmaxf(rm1, fmaxf(sc[mt][nt][2], sc[mt][nt][3]));
            }
            rm0 = fmaxf(rm0, __shfl_xor_sync(0xffffffffu, rm0, 1));
            rm0 = fmaxf(rm0, __shfl_xor_sync(0xffffffffu, rm0, 2));
            rm1 = fmaxf(rm1, __shfl_xor_sync(0xffffffffu, rm1, 1));
            rm1 = fmaxf(rm1, __shfl_xor_sync(0xffffffffu, rm1, 2));

            float mn0 = fmaxf(mrow[mt][0], rm0), mn1 = fmaxf(mrow[mt][1], rm1);
            float c0 = __expf(mrow[mt][0] - mn0), c1 = __expf(mrow[mt][1] - mn1);
            float rs0 = 0.f, rs1 = 0.f;
#pragma unroll
            for (int nt = 0; nt < 8; nt++) {
                sc[mt][nt][0] = __expf(sc[mt][nt][0] - mn0);
                sc[mt][nt][1] = __expf(sc[mt][nt][1] - mn0);
                sc[mt][nt][2] = __expf(sc[mt][nt][2] - mn1);
                sc[mt][nt][3] = __expf(sc[mt][nt][3] - mn1);
                rs0 += sc[mt][nt][0] + sc[mt][nt][1];
                rs1 += sc[mt][nt][2] + sc[mt][nt][3];
            }
            rs0 += __shfl_xor_sync(0xffffffffu, rs0, 1);
            rs0 += __shfl_xor_sync(0xffffffffu, rs0, 2);
            rs1 += __shfl_xor_sync(0xffffffffu, rs1, 1);
            rs1 += __shfl_xor_sync(0xffffffffu, rs1, 2);

            lrow[mt][0] = lrow[mt][0] * c0 + rs0;
            lrow[mt][1] = lrow[mt][1] * c1 + rs1;
            mrow[mt][0] = mn0;
            mrow[mt][1] = mn1;

            // rescale O accumulators
#pragma unroll
            for (int dt = 0; dt < 8; dt++) {
                o[mt][dt][0] *= c0; o[mt][dt][1] *= c0;
                o[mt][dt][2] *= c1; o[mt][dt][3] *= c1;
            }

            // write P to smem (fp16); PV reads only this warp's rows
#pragma unroll
            for (int nt = 0; nt < 8; nt++) {
                __half2 h0 = __floats2half2_rn(sc[mt][nt][0], sc[mt][nt][1]);
                __half2 h1 = __floats2half2_rn(sc[mt][nt][2], sc[mt][nt][3]);
                *(__half2*)(Ps + (q0 + mt * 16) * APADH + nt * 8 + 2 * c) = h0;
                *(__half2*)(Ps + (q0 + mt * 16 + 8) * APADH + nt * 8 + 2 * c) = h1;
            }
        }
        __syncwarp();

        // O += P @ V : 4 ksteps of k16; V fragments via ldmatrix.x2.trans
#pragma unroll
        for (int s0 = 0; s0 < 64; s0 += 16) {
            unsigned af[2][4];
#pragma unroll
            for (int mt = 0; mt < 2; mt++) {
                const __half* pp = Ps + (q0 + mt * 16) * APADH + s0 + 2 * c;
                af[mt][0] = *(const unsigned*)pp;
                af[mt][1] = *(const unsigned*)(pp + 8 * APADH);
                af[mt][2] = *(const unsigned*)(pp + 8);
                af[mt][3] = *(const unsigned*)(pp + 8 * APADH + 8);
            }
            unsigned row_addr = vs_base + (unsigned)(s0 + (lane & 15)) * (APADH * 2);
#pragma unroll
            for (int dt = 0; dt < 8; dt++) {
                unsigned b0, b1;
                asm volatile(
                    "ldmatrix.sync.aligned.m8n8.x2.trans.shared.b16 {%0,%1}, [%2];"
                    : "=r"(b0), "=r"(b1) : "r"(row_addr + dt * 16));
                unsigned bf[2] = {b0, b1};
                mma_fp16(o[0][dt], af[0], bf);
                mma_fp16(o[1][dt], af[1], bf);
            }
        }
        __syncthreads();
    }

    // epilogue: normalize and store
#pragma unroll
    for (int mt = 0; mt < 2; mt++) {
        float inv0 = 1.0f / lrow[mt][0], inv1 = 1.0f / lrow[mt][1];
#pragma unroll
        for (int dt = 0; dt < 8; dt++) {
            int col = dt * 8 + c * 2;
            float2 v0, v1;
            v0.x = o[mt][dt][0] * inv0; v0.y = o[mt][dt][1] * inv0;
            v1.x = o[mt][dt][2] * inv1; v1.y = o[mt][dt][3] * inv1;
            *(float2*)(Ob + (size_t)(q0 + mt * 16) * D_ + col) = v0;
            *(float2*)(Ob + (size_t)(q0 + mt * 16 + 8) * D_ + col) = v1;
        }
    }
}

// ---------------------------------------------------------------------------
// Launch. Inputs: x, context, context_mask(int32), wq, bq, wkv, bkv, wp, bp
// ---------------------------------------------------------------------------
extern "C" void kernel_launch(void* const* d_in, const int* in_sizes, int n_in,
                              void* d_out, int out_size)
{
    const float* x = (const float*)d_in[0];
    const float* ctx = (const float*)d_in[1];
    const int* mask = (const int*)d_in[2];
    const float* wq = (const float*)d_in[3];
    const float* bq = (const float*)d_in[4];
    const float* wkv = (const float*)d_in[5];
    const float* bkv = (const float*)d_in[6];
    const float* wp = (const float*)d_in[7];
    const float* bp = (const float*)d_in[8];
    float* out = (float*)d_out;

    float *Qp, *KVp, *Op;
    cudaGetSymbolAddress((void**)&Qp, g_Q);
    cudaGetSymbolAddress((void**)&KVp, g_KV);
    cudaGetSymbolAddress((void**)&Op, g_O);

    int gemm_smem = 4 * GTILEH * (int)sizeof(__half);   // 40960
    int attn_smem = ATTN_SMEM_BYTES;                    // ~94KB

    cudaFuncSetAttribute((const void*)gemm_fp16<512>,
                         cudaFuncAttributeMaxDynamicSharedMemorySize, gemm_smem);
    cudaFuncSetAttribute((const void*)attn_fp16,
                         cudaFuncAttributeMaxDynamicSharedMemorySize, attn_smem);

    // Q projection: [B*N, D] x [D, D]^T
    gemm_fp16<512><<<dim3(D_ / 128, (B_ * N_) / 128), 256, gemm_smem>>>(x, wq, bq, Qp, B_ * N_, D_);
    // KV projection: [B*S, D] x [2D, D]^T
    gemm_fp16<512><<<dim3((2 * D_) / 128, (B_ * S_) / 128), 256, gemm_smem>>>(ctx, wkv, bkv, KVp, B_ * S_, 2 * D_);
    // attention
    attn_fp16<<<dim3(N_ / QT, H_, B_), 256, attn_smem>>>(Qp, KVp, mask, Op);
    // output projection
    gemm_fp16<512><<<dim3(D_ / 128, (B_ * N_) / 128), 256, gemm_smem>>>(Op, wp, bp, out, B_ * N_, D_);
}

// round 16
// speedup vs baseline: 1.6727x; 1.0227x over previous
#include <cuda_runtime.h>
#include <cuda_fp16.h>
#include <cstdint>
#include <math.h>

// Problem constants
#define B_ 8
#define N_ 4096
#define S_ 512
#define D_ 512
#define H_ 8
#define HD_ 64

// Scratch (allocation-free rule: __device__ globals)
__device__ float g_Q[(size_t)B_ * N_ * D_];
__device__ float g_KV[(size_t)B_ * S_ * 2 * D_];
__device__ float g_O[(size_t)B_ * N_ * D_];

// ---------------------------------------------------------------------------
// fp16 mma helpers (m16n8k16, fp32 accumulate)
// ---------------------------------------------------------------------------
__device__ __forceinline__ void mma_fp16(float* d, const unsigned* a, const unsigned* b) {
    asm volatile(
        "mma.sync.aligned.m16n8k16.row.col.f32.f16.f16.f32 "
        "{%0,%1,%2,%3}, {%4,%5,%6,%7}, {%8,%9}, {%0,%1,%2,%3};\n"
        : "+f"(d[0]), "+f"(d[1]), "+f"(d[2]), "+f"(d[3])
        : "r"(a[0]), "r"(a[1]), "r"(a[2]), "r"(a[3]), "r"(b[0]), "r"(b[1]));
}

#define LDMX4(r0, r1, r2, r3, addr) \
    asm volatile("ldmatrix.sync.aligned.m8n8.x4.shared.b16 {%0,%1,%2,%3}, [%4];" \
                 : "=r"(r0), "=r"(r1), "=r"(r2), "=r"(r3) : "r"(addr))

__device__ __forceinline__ unsigned h2u(__half2 h) {
    return *(unsigned*)&h;
}

__device__ __forceinline__ unsigned smem_u32(const void* p) {
    unsigned a;
    asm("{ .reg .u64 t; cvta.to.shared.u64 t, %1; cvt.u32.u64 %0, t; }"
        : "=r"(a) : "l"(p));
    return a;
}

// ---------------------------------------------------------------------------
// GEMM: C[m][n] = sum_k A[m][k] * W[n][k] + bias[n]   (fp16 mma, fp32 accum)
// BM=BN=128, BK=32. 256 threads = 8 warps (2m x 4n), warp tile 64x32.
// Rows of 40 halves (80 B): ldmatrix-conflict-free (8-row banks disjoint).
// All fragments via ldmatrix.x4.
// ---------------------------------------------------------------------------
#define GPADH 40
#define GTILEH (128 * GPADH)

template <int KD>
__global__ __launch_bounds__(256, 2) void gemm_fp16(
    const float* __restrict__ A, const float* __restrict__ W,
    const float* __restrict__ bias, float* __restrict__ C,
    int M, int Nd)
{
    extern __shared__ __half sg[];
    __half* As = sg;                  // [2][128][40]
    __half* Ws = sg + 2 * GTILEH;     // [2][128][40]

    const int tid = threadIdx.x;
    const int lane = tid & 31;
    const int warp = tid >> 5;
    const int wm = warp >> 2;         // 0..1
    const int wn = warp & 3;          // 0..3
    const int m0 = blockIdx.y * 128;
    const int n0 = blockIdx.x * 128;
    const int g = lane >> 2;
    const int c = lane & 3;

    // ldmatrix per-lane offsets (in halves)
    const unsigned a_off = (unsigned)((wm * 64 + (lane & 15)) * GPADH + ((lane >> 4) & 1) * 8);
    const unsigned b_off = (unsigned)((wn * 32 + ((lane >> 4) & 1) * 8 + (lane & 7)) * GPADH
                                      + ((lane >> 3) & 1) * 8);
    const unsigned as_base = smem_u32(As);
    const unsigned ws_base = smem_u32(Ws);

    float acc[4][4][4];
#pragma unroll
    for (int i = 0; i < 4; i++)
#pragma unroll
        for (int j = 0; j < 4; j++)
#pragma unroll
            for (int r = 0; r < 4; r++) acc[i][j][r] = 0.f;

    float4 pa[4], pw[4];
    constexpr int nkt = KD / 32;

    // prefetch tile 0: 128 rows x 8 float4 = 1024 over 256 threads -> 4 each
#pragma unroll
    for (int l = 0; l < 4; l++) {
        int idx = tid + l * 256;
        int row = idx >> 3;
        int c4 = (idx & 7) * 4;
        pa[l] = *(const float4*)(A + (size_t)(m0 + row) * KD + c4);
        pw[l] = *(const float4*)(W + (size_t)(n0 + row) * KD + c4);
    }
#pragma unroll
    for (int l = 0; l < 4; l++) {
        int idx = tid + l * 256;
        int row = idx >> 3;
        int c4 = (idx & 7) * 4;
        uint2 ua = make_uint2(h2u(__floats2half2_rn(pa[l].x, pa[l].y)),
                              h2u(__floats2half2_rn(pa[l].z, pa[l].w)));
        uint2 uw = make_uint2(h2u(__floats2half2_rn(pw[l].x, pw[l].y)),
                              h2u(__floats2half2_rn(pw[l].z, pw[l].w)));
        *(uint2*)(As + row * GPADH + c4) = ua;
        *(uint2*)(Ws + row * GPADH + c4) = uw;
    }
    __syncthreads();

#pragma unroll 2
    for (int kt = 0; kt < nkt; kt++) {
        if (kt + 1 < nkt) {
#pragma unroll
            for (int l = 0; l < 4; l++) {
                int idx = tid + l * 256;
                int row = idx >> 3;
                int c4 = (idx & 7) * 4;
                pa[l] = *(const float4*)(A + (size_t)(m0 + row) * KD + (kt + 1) * 32 + c4);
                pw[l] = *(const float4*)(W + (size_t)(n0 + row) * KD + (kt + 1) * 32 + c4);
            }
        }
        const unsigned abuf = as_base + (unsigned)((kt & 1) * GTILEH) * 2u;
        const unsigned wbuf = ws_base + (unsigned)((kt & 1) * GTILEH) * 2u;

#pragma unroll
        for (int k0 = 0; k0 < 32; k0 += 16) {
            unsigned af[4][4], bf[4][2];
#pragma unroll
            for (int mt = 0; mt < 4; mt++) {
                unsigned addr = abuf + (a_off + (unsigned)(mt * 16 * GPADH + k0)) * 2u;
                LDMX4(af[mt][0], af[mt][1], af[mt][2], af[mt][3], addr);
            }
#pragma unroll
            for (int np = 0; np < 2; np++) {
                unsigned addr = wbuf + (b_off + (unsigned)(np * 16 * GPADH + k0)) * 2u;
                LDMX4(bf[2 * np][0], bf[2 * np][1], bf[2 * np + 1][0], bf[2 * np + 1][1], addr);
            }
#pragma unroll
            for (int mt = 0; mt < 4; mt++)
#pragma unroll
                for (int nt = 0; nt < 4; nt++)
                    mma_fp16(acc[mt][nt], af[mt], bf[nt]);
        }
        // Store next tile into the OTHER buffer (readers finished before the
        // previous barrier), then one barrier.
        if (kt + 1 < nkt) {
            __half* Ad = As + ((kt + 1) & 1) * GTILEH;
            __half* Wd = Ws + ((kt + 1) & 1) * GTILEH;
#pragma unroll
            for (int l = 0; l < 4; l++) {
                int idx = tid + l * 256;
                int row = idx >> 3;
                int c4 = (idx & 7) * 4;
                uint2 ua = make_uint2(h2u(__floats2half2_rn(pa[l].x, pa[l].y)),
                                      h2u(__floats2half2_rn(pa[l].z, pa[l].w)));
                uint2 uw = make_uint2(h2u(__floats2half2_rn(pw[l].x, pw[l].y)),
                                      h2u(__floats2half2_rn(pw[l].z, pw[l].w)));
                *(uint2*)(Ad + row * GPADH + c4) = ua;
                *(uint2*)(Wd + row * GPADH + c4) = uw;
            }
            __syncthreads();
        }
    }

    // epilogue + bias (accumulator layout unchanged)
#pragma unroll
    for (int mt = 0; mt < 4; mt++) {
        int row0 = m0 + wm * 64 + mt * 16 + g;
#pragma unroll
        for (int nt = 0; nt < 4; nt++) {
            int col = n0 + wn * 32 + nt * 8 + c * 2;
            float2 bb = *(const float2*)(bias + col);
            float2 v0, v1;
            v0.x = acc[mt][nt][0] + bb.x;
            v0.y = acc[mt][nt][1] + bb.y;
            v1.x = acc[mt][nt][2] + bb.x;
            v1.y = acc[mt][nt][3] + bb.y;
            *(float2*)(C + (size_t)row0 * Nd + col) = v0;
            *(float2*)(C + (size_t)(row0 + 8) * Nd + col) = v1;
        }
    }
}

// ---------------------------------------------------------------------------
// Flash attention, fp16 mma + ldmatrix everywhere. CTA = 256 queries of one
// (b,h). 256 threads (8 warps); warp owns 32 q-rows (mt=0..1). S-tiles of 64.
// Rows of 72 halves (144 B): ldmatrix-conflict-free.
// ---------------------------------------------------------------------------
#define APADH 72
#define QT 256
// half-offsets in dynamic smem
#define QS_H 0
#define KS_H (QT * APADH)
#define PS_H (KS_H + 64 * APADH)
#define VS_H (PS_H + QT * APADH)
#define MA_BYTE ((VS_H + 64 * APADH) * 2)
#define ATTN_SMEM_BYTES (MA_BYTE + 512 * 4)

__global__ __launch_bounds__(256, 1) void attn_fp16(
    const float* __restrict__ Q, const float* __restrict__ KV,
    const int* __restrict__ mask, float* __restrict__ O)
{
    extern __shared__ __half sh[];
    __half* Qs = sh + QS_H;     // [256][72]
    __half* Ks = sh + KS_H;     // [64][72]
    __half* Ps = sh + PS_H;     // [256][72]
    __half* Vs = sh + VS_H;     // [64][72], natural [s][d]
    float* mAdd = (float*)((char*)sh + MA_BYTE);   // [512]

    const int tid = threadIdx.x;
    const int lane = tid & 31;
    const int warp = tid >> 5;
    const int g = lane >> 2;
    const int c = lane & 3;
    const int n0 = blockIdx.x * QT;
    const int h = blockIdx.y;
    const int b = blockIdx.z;

    const float* Qb = Q + ((size_t)b * N_ + n0) * D_ + h * HD_;
    const float* Kb = KV + (size_t)b * S_ * (2 * D_) + h * HD_;
    const float* Vb = Kb + D_;
    const int* mb = mask + b * S_;
    float* Ob = O + ((size_t)b * N_ + n0) * D_ + h * HD_;

    const unsigned qs_base = smem_u32(Qs);
    const unsigned ks_base = smem_u32(Ks);
    const unsigned ps_base = smem_u32(Ps);
    const unsigned vs_base = smem_u32(Vs);

    // ldmatrix per-lane offsets (halves)
    // A-style (Q, P): row = warp*32 + mt*16 + (lane&15), koff = ((lane>>4)&1)*8
    const unsigned aq_off = (unsigned)((warp * 32 + (lane & 15)) * APADH + ((lane >> 4) & 1) * 8);
    // B-style (K): row = np*16 + ((lane>>4)&1)*8 + (lane&7), koff = ((lane>>3)&1)*8
    const unsigned bk_off = (unsigned)((((lane >> 4) & 1) * 8 + (lane & 7)) * APADH
                                       + ((lane >> 3) & 1) * 8);

    // load Q tile (pre-scaled by 0.125), cvt to fp16.
#pragma unroll
    for (int l = 0; l < 16; l++) {
        int idx = tid + l * 256;
        int q = idx >> 4;
        int d4 = (idx & 15) * 4;
        float4 v = *(const float4*)(Qb + (size_t)q * D_ + d4);
        uint2 u = make_uint2(
            h2u(__floats2half2_rn(v.x * 0.125f, v.y * 0.125f)),
            h2u(__floats2half2_rn(v.z * 0.125f, v.w * 0.125f)));
        *(uint2*)(Qs + q * APADH + d4) = u;
    }
    for (int s = tid; s < S_; s += 256) mAdd[s] = mb[s] ? -1e5f : 0.f;

    float o[2][8][4];
#pragma unroll
    for (int mt = 0; mt < 2; mt++)
#pragma unroll
        for (int i = 0; i < 8; i++)
#pragma unroll
            for (int r = 0; r < 4; r++) o[mt][i][r] = 0.f;
    float mrow[2][2], lrow[2][2];
#pragma unroll
    for (int mt = 0; mt < 2; mt++) {
        mrow[mt][0] = -1e30f; mrow[mt][1] = -1e30f;
        lrow[mt][0] = 0.f;    lrow[mt][1] = 0.f;
    }

    const int q0 = warp * 32 + g;   // accumulator row map; mt block adds +16

    __syncthreads();

    for (int st = 0; st < S_; st += 64) {
        // load K and V tiles (natural [s][d] layout, fp16)
#pragma unroll
        for (int l = 0; l < 4; l++) {
            int idx = tid + l * 256;
            int s = idx >> 4;
            int d4 = (idx & 15) * 4;
            float4 vk = *(const float4*)(Kb + (size_t)(st + s) * (2 * D_) + d4);
            uint2 uk = make_uint2(h2u(__floats2half2_rn(vk.x, vk.y)),
                                  h2u(__floats2half2_rn(vk.z, vk.w)));
            *(uint2*)(Ks + s * APADH + d4) = uk;
            float4 vv = *(const float4*)(Vb + (size_t)(st + s) * (2 * D_) + d4);
            uint2 uv = make_uint2(h2u(__floats2half2_rn(vv.x, vv.y)),
                                  h2u(__floats2half2_rn(vv.z, vv.w)));
            *(uint2*)(Vs + s * APADH + d4) = uv;
        }
        __syncthreads();

        // QK^T: scores [32q x 64s] per warp, 4 ksteps of k16
        float sc[2][8][4];
#pragma unroll
        for (int mt = 0; mt < 2; mt++)
#pragma unroll
            for (int nt = 0; nt < 8; nt++)
#pragma unroll
                for (int r = 0; r < 4; r++) sc[mt][nt][r] = 0.f;

#pragma unroll
        for (int k0 = 0; k0 < 64; k0 += 16) {
            unsigned af[2][4], bf[8][2];
#pragma unroll
            for (int mt = 0; mt < 2; mt++) {
                unsigned addr = qs_base + (aq_off + (unsigned)(mt * 16 * APADH + k0)) * 2u;
                LDMX4(af[mt][0], af[mt][1], af[mt][2], af[mt][3], addr);
            }
#pragma unroll
            for (int np = 0; np < 4; np++) {
                unsigned addr = ks_base + (bk_off + (unsigned)(np * 16 * APADH + k0)) * 2u;
                LDMX4(bf[2 * np][0], bf[2 * np][1], bf[2 * np + 1][0], bf[2 * np + 1][1], addr);
            }
#pragma unroll
            for (int nt = 0; nt < 8; nt++) {
                mma_fp16(sc[0][nt], af[0], bf[nt]);
                mma_fp16(sc[1][nt], af[1], bf[nt]);
            }
        }

        // mask + online softmax, per mt block (rows q0+mt*16, +8)
#pragma unroll
        for (int mt = 0; mt < 2; mt++) {
            float rm0 = -1e30f, rm1 = -1e30f;
#pragma unroll
            for (int nt = 0; nt < 8; nt++) {
                int col = st + nt * 8 + c * 2;
                float a0 = mAdd[col], a1 = mAdd[col + 1];
                sc[mt][nt][0] += a0; sc[mt][nt][1] += a1;
                sc[mt][nt][2] += a0; sc[mt][nt][3] += a1;
                rm0 = fmaxf(rm0, fmaxf(sc[mt][nt][0], sc[mt][nt][1]));
                rm1 = fmaxf(rm1, fmaxf(sc[mt][nt][2], sc[mt][nt][3]));
            }
            rm0 = fmaxf(rm0, __shfl_xor_sync(0xffffffffu, rm0, 1));
            rm0 = fmaxf(rm0, __shfl_xor_sync(0xffffffffu, rm0, 2));
            rm1 = fmaxf(rm1, __shfl_xor_sync(0xffffffffu, rm1, 1));
            rm1 = fmaxf(rm1, __shfl_xor_sync(0xffffffffu, rm1, 2));

            float mn0 = fmaxf(mrow[mt][0], rm0), mn1 = fmaxf(mrow[mt][1], rm1);
            float c0 = __expf(mrow[mt][0] - mn0), c1 = __expf(mrow[mt][1] - mn1);
            float rs0 = 0.f, rs1 = 0.f;
#pragma unroll
            for (int nt = 0; nt < 8; nt++) {
                sc[mt][nt][0] = __expf(sc[mt][nt][0] - mn0);
                sc[mt][nt][1] = __expf(sc[mt][nt][1] - mn0);
                sc[mt][nt][2] = __expf(sc[mt][nt][2] - mn1);
                sc[mt][nt][3] = __expf(sc[mt][nt][3] - mn1);
                rs0 += sc[mt][nt][0] + sc[mt][nt][1];
                rs1 += sc[mt][nt][2] + sc[mt][nt][3];
            }
            rs0 += __shfl_xor_sync(0xffffffffu, rs0, 1);
            rs0 += __shfl_xor_sync(0xffffffffu, rs0, 2);
            rs1 += __shfl_xor_sync(0xffffffffu, rs1, 1);
            rs1 += __shfl_xor_sync(0xffffffffu, rs1, 2);

            lrow[mt][0] = lrow[mt][0] * c0 + rs0;
            lrow[mt][1] = lrow[mt][1] * c1 + rs1;
            mrow[mt][0] = mn0;
            mrow[mt][1] = mn1;

            // rescale O accumulators
#pragma unroll
            for (int dt = 0; dt < 8; dt++) {
                o[mt][dt][0] *= c0; o[mt][dt][1] *= c0;
                o[mt][dt][2] *= c1; o[mt][dt][3] *= c1;
            }

            // write P to smem (fp16); PV reads only this warp's rows
#pragma unroll
            for (int nt = 0; nt < 8; nt++) {
                __half2 h0 = __floats2half2_rn(sc[mt][nt][0], sc[mt][nt][1]);
                __half2 h1 = __floats2half2_rn(sc[mt][nt][2], sc[mt][nt][3]);
                *(__half2*)(Ps + (q0 + mt * 16) * APADH + nt * 8 + 2 * c) = h0;
                *(__half2*)(Ps + (q0 + mt * 16 + 8) * APADH + nt * 8 + 2 * c) = h1;
            }
        }
        __syncwarp();

        // O += P @ V : 4 ksteps of k16; P via ldmatrix.x4, V via ldmatrix.x2.trans
#pragma unroll
        for (int s0 = 0; s0 < 64; s0 += 16) {
            unsigned af[2][4];
#pragma unroll
            for (int mt = 0; mt < 2; mt++) {
                unsigned addr = ps_base + (aq_off + (unsigned)(mt * 16 * APADH + s0)) * 2u;
                LDMX4(af[mt][0], af[mt][1], af[mt][2], af[mt][3], addr);
            }
            unsigned row_addr = vs_base + (unsigned)(s0 + (lane & 15)) * (APADH * 2);
#pragma unroll
            for (int dt = 0; dt < 8; dt++) {
                unsigned b0, b1;
                asm volatile(
                    "ldmatrix.sync.aligned.m8n8.x2.trans.shared.b16 {%0,%1}, [%2];"
                    : "=r"(b0), "=r"(b1) : "r"(row_addr + dt * 16));
                unsigned bf[2] = {b0, b1};
                mma_fp16(o[0][dt], af[0], bf);
                mma_fp16(o[1][dt], af[1], bf);
            }
        }
        __syncthreads();
    }

    // epilogue: normalize and store
#pragma unroll
    for (int mt = 0; mt < 2; mt++) {
        float inv0 = 1.0f / lrow[mt][0], inv1 = 1.0f / lrow[mt][1];
#pragma unroll
        for (int dt = 0; dt < 8; dt++) {
            int col = dt * 8 + c * 2;
            float2 v0, v1;
            v0.x = o[mt][dt][0] * inv0; v0.y = o[mt][dt][1] * inv0;
            v1.x = o[mt][dt][2] * inv1; v1.y = o[mt][dt][3] * inv1;
            *(float2*)(Ob + (size_t)(q0 + mt * 16) * D_ + col) = v0;
            *(float2*)(Ob + (size_t)(q0 + mt * 16 + 8) * D_ + col) = v1;
        }
    }
}

// ---------------------------------------------------------------------------
// Launch. Inputs: x, context, context_mask(int32), wq, bq, wkv, bkv, wp, bp
// ---------------------------------------------------------------------------
extern "C" void kernel_launch(void* const* d_in, const int* in_sizes, int n_in,
                              void* d_out, int out_size)
{
    const float* x = (const float*)d_in[0];
    const float* ctx = (const float*)d_in[1];
    const int* mask = (const int*)d_in[2];
    const float* wq = (const float*)d_in[3];
    const float* bq = (const float*)d_in[4];
    const float* wkv = (const float*)d_in[5];
    const float* bkv = (const float*)d_in[6];
    const float* wp = (const float*)d_in[7];
    const float* bp = (const float*)d_in[8];
    float* out = (float*)d_out;

    float *Qp, *KVp, *Op;
    cudaGetSymbolAddress((void**)&Qp, g_Q);
    cudaGetSymbolAddress((void**)&KVp, g_KV);
    cudaGetSymbolAddress((void**)&Op, g_O);

    int gemm_smem = 4 * GTILEH * (int)sizeof(__half);   // 40960
    int attn_smem = ATTN_SMEM_BYTES;                    // ~94KB

    cudaFuncSetAttribute((const void*)gemm_fp16<512>,
                         cudaFuncAttributeMaxDynamicSharedMemorySize, gemm_smem);
    cudaFuncSetAttribute((const void*)attn_fp16,
                         cudaFuncAttributeMaxDynamicSharedMemorySize, attn_smem);

    // Q projection: [B*N, D] x [D, D]^T
    gemm_fp16<512><<<dim3(D_ / 128, (B_ * N_) / 128), 256, gemm_smem>>>(x, wq, bq, Qp, B_ * N_, D_);
    // KV projection: [B*S, D] x [2D, D]^T
    gemm_fp16<512><<<dim3((2 * D_) / 128, (B_ * S_) / 128), 256, gemm_smem>>>(ctx, wkv, bkv, KVp, B_ * S_, 2 * D_);
    // attention
    attn_fp16<<<dim3(N_ / QT, H_, B_), 256, attn_smem>>>(Qp, KVp, mask, Op);
    // output projection
    gemm_fp16<512><<<dim3(D_ / 128, (B_ * N_) / 128), 256, gemm_smem>>>(Op, wp, bp, out, B_ * N_, D_);
}

// round 17
// speedup vs baseline: 1.7328x; 1.0359x over previous
#include <cuda_runtime.h>
#include <cuda_fp16.h>
#include <cstdint>
#include <math.h>

// Problem constants
#define B_ 8
#define N_ 4096
#define S_ 512
#define D_ 512
#define H_ 8
#define HD_ 64

// Scratch (allocation-free rule: __device__ globals) — fp16 at rest
__device__ __half g_Qh[(size_t)B_ * N_ * D_];        // 32 MB
__device__ __half g_KVh[(size_t)B_ * S_ * 2 * D_];   // 8 MB
__device__ __half g_Oh[(size_t)B_ * N_ * D_];        // 32 MB

// ---------------------------------------------------------------------------
// fp16 mma helpers (m16n8k16, fp32 accumulate)
// ---------------------------------------------------------------------------
__device__ __forceinline__ void mma_fp16(float* d, const unsigned* a, const unsigned* b) {
    asm volatile(
        "mma.sync.aligned.m16n8k16.row.col.f32.f16.f16.f32 "
        "{%0,%1,%2,%3}, {%4,%5,%6,%7}, {%8,%9}, {%0,%1,%2,%3};\n"
        : "+f"(d[0]), "+f"(d[1]), "+f"(d[2]), "+f"(d[3])
        : "r"(a[0]), "r"(a[1]), "r"(a[2]), "r"(a[3]), "r"(b[0]), "r"(b[1]));
}

#define LDMX4(r0, r1, r2, r3, addr) \
    asm volatile("ldmatrix.sync.aligned.m8n8.x4.shared.b16 {%0,%1,%2,%3}, [%4];" \
                 : "=r"(r0), "=r"(r1), "=r"(r2), "=r"(r3) : "r"(addr))

__device__ __forceinline__ unsigned h2u(__half2 h) {
    return *(unsigned*)&h;
}

__device__ __forceinline__ unsigned smem_u32(const void* p) {
    unsigned a;
    asm("{ .reg .u64 t; cvta.to.shared.u64 t, %1; cvt.u32.u64 %0, t; }"
        : "=r"(a) : "l"(p));
    return a;
}

// ---------------------------------------------------------------------------
// GEMM: C[m][n] = sum_k A[m][k] * W[n][k] + bias[n]   (fp16 mma, fp32 accum)
// BM=BN=128, BK=32. 256 threads = 8 warps (2m x 4n), warp tile 64x32.
// A_HALF: A is fp16 (direct copy to smem). C_HALF: C written as fp16.
// Rows of 40 halves: ldmatrix-conflict-free. All fragments via ldmatrix.x4.
// ---------------------------------------------------------------------------
#define GPADH 40
#define GTILEH (128 * GPADH)

template <int KD, bool A_HALF, bool C_HALF>
__global__ __launch_bounds__(256, 2) void gemm_fp16(
    const void* __restrict__ Av, const float* __restrict__ W,
    const float* __restrict__ bias, void* __restrict__ Cv,
    int M, int Nd)
{
    extern __shared__ __half sg[];
    __half* As = sg;                  // [2][128][40]
    __half* Ws = sg + 2 * GTILEH;     // [2][128][40]

    const int tid = threadIdx.x;
    const int lane = tid & 31;
    const int warp = tid >> 5;
    const int wm = warp >> 2;         // 0..1
    const int wn = warp & 3;          // 0..3
    const int m0 = blockIdx.y * 128;
    const int n0 = blockIdx.x * 128;
    const int g = lane >> 2;
    const int c = lane & 3;

    const unsigned a_off = (unsigned)((wm * 64 + (lane & 15)) * GPADH + ((lane >> 4) & 1) * 8);
    const unsigned b_off = (unsigned)((wn * 32 + ((lane >> 4) & 1) * 8 + (lane & 7)) * GPADH
                                      + ((lane >> 3) & 1) * 8);
    const unsigned as_base = smem_u32(As);
    const unsigned ws_base = smem_u32(Ws);

    float acc[4][4][4];
#pragma unroll
    for (int i = 0; i < 4; i++)
#pragma unroll
        for (int j = 0; j < 4; j++)
#pragma unroll
            for (int r = 0; r < 4; r++) acc[i][j][r] = 0.f;

    const float* Af = (const float*)Av;
    const __half* Ah = (const __half*)Av;
    float4 pa[4], pw[4];
    uint4 ph[2];
    constexpr int nkt = KD / 32;

    // ---- prefetch tile 0 ----
    if (A_HALF) {
        // 128 rows x 4 uint4(8 halves) = 512 over 256 threads -> 2 each
#pragma unroll
        for (int l = 0; l < 2; l++) {
            int idx = tid + l * 256;
            int row = idx >> 2;
            int c8 = (idx & 3) * 8;
            ph[l] = *(const uint4*)(Ah + (size_t)(m0 + row) * KD + c8);
        }
    } else {
#pragma unroll
        for (int l = 0; l < 4; l++) {
            int idx = tid + l * 256;
            int row = idx >> 3;
            int c4 = (idx & 7) * 4;
            pa[l] = *(const float4*)(Af + (size_t)(m0 + row) * KD + c4);
        }
    }
#pragma unroll
    for (int l = 0; l < 4; l++) {
        int idx = tid + l * 256;
        int row = idx >> 3;
        int c4 = (idx & 7) * 4;
        pw[l] = *(const float4*)(W + (size_t)(n0 + row) * KD + c4);
    }
    if (A_HALF) {
#pragma unroll
        for (int l = 0; l < 2; l++) {
            int idx = tid + l * 256;
            int row = idx >> 2;
            int c8 = (idx & 3) * 8;
            *(uint4*)(As + row * GPADH + c8) = ph[l];
        }
    } else {
#pragma unroll
        for (int l = 0; l < 4; l++) {
            int idx = tid + l * 256;
            int row = idx >> 3;
            int c4 = (idx & 7) * 4;
            uint2 ua = make_uint2(h2u(__floats2half2_rn(pa[l].x, pa[l].y)),
                                  h2u(__floats2half2_rn(pa[l].z, pa[l].w)));
            *(uint2*)(As + row * GPADH + c4) = ua;
        }
    }
#pragma unroll
    for (int l = 0; l < 4; l++) {
        int idx = tid + l * 256;
        int row = idx >> 3;
        int c4 = (idx & 7) * 4;
        uint2 uw = make_uint2(h2u(__floats2half2_rn(pw[l].x, pw[l].y)),
                              h2u(__floats2half2_rn(pw[l].z, pw[l].w)));
        *(uint2*)(Ws + row * GPADH + c4) = uw;
    }
    __syncthreads();

#pragma unroll 2
    for (int kt = 0; kt < nkt; kt++) {
        if (kt + 1 < nkt) {
            if (A_HALF) {
#pragma unroll
                for (int l = 0; l < 2; l++) {
                    int idx = tid + l * 256;
                    int row = idx >> 2;
                    int c8 = (idx & 3) * 8;
                    ph[l] = *(const uint4*)(Ah + (size_t)(m0 + row) * KD + (kt + 1) * 32 + c8);
                }
            } else {
#pragma unroll
                for (int l = 0; l < 4; l++) {
                    int idx = tid + l * 256;
                    int row = idx >> 3;
                    int c4 = (idx & 7) * 4;
                    pa[l] = *(const float4*)(Af + (size_t)(m0 + row) * KD + (kt + 1) * 32 + c4);
                }
            }
#pragma unroll
            for (int l = 0; l < 4; l++) {
                int idx = tid + l * 256;
                int row = idx >> 3;
                int c4 = (idx & 7) * 4;
                pw[l] = *(const float4*)(W + (size_t)(n0 + row) * KD + (kt + 1) * 32 + c4);
            }
        }
        const unsigned abuf = as_base + (unsigned)((kt & 1) * GTILEH) * 2u;
        const unsigned wbuf = ws_base + (unsigned)((kt & 1) * GTILEH) * 2u;

#pragma unroll
        for (int k0 = 0; k0 < 32; k0 += 16) {
            unsigned af[4][4], bf[4][2];
#pragma unroll
            for (int mt = 0; mt < 4; mt++) {
                unsigned addr = abuf + (a_off + (unsigned)(mt * 16 * GPADH + k0)) * 2u;
                LDMX4(af[mt][0], af[mt][1], af[mt][2], af[mt][3], addr);
            }
#pragma unroll
            for (int np = 0; np < 2; np++) {
                unsigned addr = wbuf + (b_off + (unsigned)(np * 16 * GPADH + k0)) * 2u;
                LDMX4(bf[2 * np][0], bf[2 * np][1], bf[2 * np + 1][0], bf[2 * np + 1][1], addr);
            }
#pragma unroll
            for (int mt = 0; mt < 4; mt++)
#pragma unroll
                for (int nt = 0; nt < 4; nt++)
                    mma_fp16(acc[mt][nt], af[mt], bf[nt]);
        }
        if (kt + 1 < nkt) {
            __half* Ad = As + ((kt + 1) & 1) * GTILEH;
            __half* Wd = Ws + ((kt + 1) & 1) * GTILEH;
            if (A_HALF) {
#pragma unroll
                for (int l = 0; l < 2; l++) {
                    int idx = tid + l * 256;
                    int row = idx >> 2;
                    int c8 = (idx & 3) * 8;
                    *(uint4*)(Ad + row * GPADH + c8) = ph[l];
                }
            } else {
#pragma unroll
                for (int l = 0; l < 4; l++) {
                    int idx = tid + l * 256;
                    int row = idx >> 3;
                    int c4 = (idx & 7) * 4;
                    uint2 ua = make_uint2(h2u(__floats2half2_rn(pa[l].x, pa[l].y)),
                                          h2u(__floats2half2_rn(pa[l].z, pa[l].w)));
                    *(uint2*)(Ad + row * GPADH + c4) = ua;
                }
            }
#pragma unroll
            for (int l = 0; l < 4; l++) {
                int idx = tid + l * 256;
                int row = idx >> 3;
                int c4 = (idx & 7) * 4;
                uint2 uw = make_uint2(h2u(__floats2half2_rn(pw[l].x, pw[l].y)),
                                      h2u(__floats2half2_rn(pw[l].z, pw[l].w)));
                *(uint2*)(Wd + row * GPADH + c4) = uw;
            }
            __syncthreads();
        }
    }

    // epilogue + bias
#pragma unroll
    for (int mt = 0; mt < 4; mt++) {
        int row0 = m0 + wm * 64 + mt * 16 + g;
#pragma unroll
        for (int nt = 0; nt < 4; nt++) {
            int col = n0 + wn * 32 + nt * 8 + c * 2;
            float2 bb = *(const float2*)(bias + col);
            float x0 = acc[mt][nt][0] + bb.x;
            float y0 = acc[mt][nt][1] + bb.y;
            float x1 = acc[mt][nt][2] + bb.x;
            float y1 = acc[mt][nt][3] + bb.y;
            if (C_HALF) {
                __half* C = (__half*)Cv;
                *(__half2*)(C + (size_t)row0 * Nd + col) = __floats2half2_rn(x0, y0);
                *(__half2*)(C + (size_t)(row0 + 8) * Nd + col) = __floats2half2_rn(x1, y1);
            } else {
                float* C = (float*)Cv;
                *(float2*)(C + (size_t)row0 * Nd + col) = make_float2(x0, y0);
                *(float2*)(C + (size_t)(row0 + 8) * Nd + col) = make_float2(x1, y1);
            }
        }
    }
}

// ---------------------------------------------------------------------------
// Flash attention, fp16 in/out. CTA = 256 queries of one (b,h). 256 threads
// (8 warps); warp owns 32 q-rows (mt=0..1). S-tiles of 64.
// Q/K/V loaded as raw fp16 uint4 copies (no conversion). Output fp16.
// Rows of 72 halves: ldmatrix-conflict-free.
// ---------------------------------------------------------------------------
#define APADH 72
#define QT 256
#define QS_H 0
#define KS_H (QT * APADH)
#define PS_H (KS_H + 64 * APADH)
#define VS_H (PS_H + QT * APADH)
#define MA_BYTE ((VS_H + 64 * APADH) * 2)
#define ATTN_SMEM_BYTES (MA_BYTE + 512 * 4)

__global__ __launch_bounds__(256, 1) void attn_fp16(
    const __half* __restrict__ Q, const __half* __restrict__ KV,
    const int* __restrict__ mask, __half* __restrict__ O)
{
    extern __shared__ __half sh[];
    __half* Qs = sh + QS_H;     // [256][72]
    __half* Ks = sh + KS_H;     // [64][72]
    __half* Ps = sh + PS_H;     // [256][72]
    __half* Vs = sh + VS_H;     // [64][72], natural [s][d]
    float* mAdd = (float*)((char*)sh + MA_BYTE);   // [512]

    const int tid = threadIdx.x;
    const int lane = tid & 31;
    const int warp = tid >> 5;
    const int g = lane >> 2;
    const int c = lane & 3;
    const int n0 = blockIdx.x * QT;
    const int h = blockIdx.y;
    const int b = blockIdx.z;

    const __half* Qb = Q + ((size_t)b * N_ + n0) * D_ + h * HD_;
    const __half* Kb = KV + (size_t)b * S_ * (2 * D_) + h * HD_;
    const __half* Vb = Kb + D_;
    const int* mb = mask + b * S_;
    __half* Ob = O + ((size_t)b * N_ + n0) * D_ + h * HD_;

    const unsigned qs_base = smem_u32(Qs);
    const unsigned ks_base = smem_u32(Ks);
    const unsigned ps_base = smem_u32(Ps);
    const unsigned vs_base = smem_u32(Vs);

    const unsigned aq_off = (unsigned)((warp * 32 + (lane & 15)) * APADH + ((lane >> 4) & 1) * 8);
    const unsigned bk_off = (unsigned)((((lane >> 4) & 1) * 8 + (lane & 7)) * APADH
                                       + ((lane >> 3) & 1) * 8);

    // load Q tile: raw fp16 copy, pre-scale by 0.125 with half2 mul.
    // 256 rows x 8 uint4(8 halves) = 2048 over 256 threads -> 8 iters.
    const __half2 scl = __floats2half2_rn(0.125f, 0.125f);
#pragma unroll
    for (int l = 0; l < 8; l++) {
        int idx = tid + l * 256;
        int q = idx >> 3;
        int d8 = (idx & 7) * 8;
        uint4 v = *(const uint4*)(Qb + (size_t)q * D_ + d8);
        __half2* hv = (__half2*)&v;
        hv[0] = __hmul2(hv[0], scl); hv[1] = __hmul2(hv[1], scl);
        hv[2] = __hmul2(hv[2], scl); hv[3] = __hmul2(hv[3], scl);
        *(uint4*)(Qs + q * APADH + d8) = v;
    }
    for (int s = tid; s < S_; s += 256) mAdd[s] = mb[s] ? -1e5f : 0.f;

    float o[2][8][4];
#pragma unroll
    for (int mt = 0; mt < 2; mt++)
#pragma unroll
        for (int i = 0; i < 8; i++)
#pragma unroll
            for (int r = 0; r < 4; r++) o[mt][i][r] = 0.f;
    float mrow[2][2], lrow[2][2];
#pragma unroll
    for (int mt = 0; mt < 2; mt++) {
        mrow[mt][0] = -1e30f; mrow[mt][1] = -1e30f;
        lrow[mt][0] = 0.f;    lrow[mt][1] = 0.f;
    }

    const int q0 = warp * 32 + g;

    __syncthreads();

    for (int st = 0; st < S_; st += 64) {
        // load K and V tiles: raw fp16 copies.
        // 64 rows x 8 uint4 = 512 over 256 threads -> 2 iters each.
#pragma unroll
        for (int l = 0; l < 2; l++) {
            int idx = tid + l * 256;
            int s = idx >> 3;
            int d8 = (idx & 7) * 8;
            *(uint4*)(Ks + s * APADH + d8) =
                *(const uint4*)(Kb + (size_t)(st + s) * (2 * D_) + d8);
            *(uint4*)(Vs + s * APADH + d8) =
                *(const uint4*)(Vb + (size_t)(st + s) * (2 * D_) + d8);
        }
        __syncthreads();

        // QK^T: scores [32q x 64s] per warp, 4 ksteps of k16
        float sc[2][8][4];
#pragma unroll
        for (int mt = 0; mt < 2; mt++)
#pragma unroll
            for (int nt = 0; nt < 8; nt++)
#pragma unroll
                for (int r = 0; r < 4; r++) sc[mt][nt][r] = 0.f;

#pragma unroll
        for (int k0 = 0; k0 < 64; k0 += 16) {
            unsigned af[2][4], bf[8][2];
#pragma unroll
            for (int mt = 0; mt < 2; mt++) {
                unsigned addr = qs_base + (aq_off + (unsigned)(mt * 16 * APADH + k0)) * 2u;
                LDMX4(af[mt][0], af[mt][1], af[mt][2], af[mt][3], addr);
            }
#pragma unroll
            for (int np = 0; np < 4; np++) {
                unsigned addr = ks_base + (bk_off + (unsigned)(np * 16 * APADH + k0)) * 2u;
                LDMX4(bf[2 * np][0], bf[2 * np][1], bf[2 * np + 1][0], bf[2 * np + 1][1], addr);
            }
#pragma unroll
            for (int nt = 0; nt < 8; nt++) {
                mma_fp16(sc[0][nt], af[0], bf[nt]);
                mma_fp16(sc[1][nt], af[1], bf[nt]);
            }
        }

        // mask + online softmax, per mt block
#pragma unroll
        for (int mt = 0; mt < 2; mt++) {
            float rm0 = -1e30f, rm1 = -1e30f;
#pragma unroll
            for (int nt = 0; nt < 8; nt++) {
                int col = st + nt * 8 + c * 2;
                float a0 = mAdd[col], a1 = mAdd[col + 1];
                sc[mt][nt][0] += a0; sc[mt][nt][1] += a1;
                sc[mt][nt][2] += a0; sc[mt][nt][3] += a1;
                rm0 = fmaxf(rm0, fmaxf(sc[mt][nt][0], sc[mt][nt][1]));
                rm1 = fmaxf(rm1, fmaxf(sc[mt][nt][2], sc[mt][nt][3]));
            }
            rm0 = fmaxf(rm0, __shfl_xor_sync(0xffffffffu, rm0, 1));
            rm0 = fmaxf(rm0, __shfl_xor_sync(0xffffffffu, rm0, 2));
            rm1 = fmaxf(rm1, __shfl_xor_sync(0xffffffffu, rm1, 1));
            rm1 = fmaxf(rm1, __shfl_xor_sync(0xffffffffu, rm1, 2));

            float mn0 = fmaxf(mrow[mt][0], rm0), mn1 = fmaxf(mrow[mt][1], rm1);
            float c0 = __expf(mrow[mt][0] - mn0), c1 = __expf(mrow[mt][1] - mn1);
            float rs0 = 0.f, rs1 = 0.f;
#pragma unroll
            for (int nt = 0; nt < 8; nt++) {
                sc[mt][nt][0] = __expf(sc[mt][nt][0] - mn0);
                sc[mt][nt][1] = __expf(sc[mt][nt][1] - mn0);
                sc[mt][nt][2] = __expf(sc[mt][nt][2] - mn1);
                sc[mt][nt][3] = __expf(sc[mt][nt][3] - mn1);
                rs0 += sc[mt][nt][0] + sc[mt][nt][1];
                rs1 += sc[mt][nt][2] + sc[mt][nt][3];
            }
            rs0 += __shfl_xor_sync(0xffffffffu, rs0, 1);
            rs0 += __shfl_xor_sync(0xffffffffu, rs0, 2);
            rs1 += __shfl_xor_sync(0xffffffffu, rs1, 1);
            rs1 += __shfl_xor_sync(0xffffffffu, rs1, 2);

            lrow[mt][0] = lrow[mt][0] * c0 + rs0;
            lrow[mt][1] = lrow[mt][1] * c1 + rs1;
            mrow[mt][0] = mn0;
            mrow[mt][1] = mn1;

#pragma unroll
            for (int dt = 0; dt < 8; dt++) {
                o[mt][dt][0] *= c0; o[mt][dt][1] *= c0;
                o[mt][dt][2] *= c1; o[mt][dt][3] *= c1;
            }

#pragma unroll
            for (int nt = 0; nt < 8; nt++) {
                __half2 h0 = __floats2half2_rn(sc[mt][nt][0], sc[mt][nt][1]);
                __half2 h1 = __floats2half2_rn(sc[mt][nt][2], sc[mt][nt][3]);
                *(__half2*)(Ps + (q0 + mt * 16) * APADH + nt * 8 + 2 * c) = h0;
                *(__half2*)(Ps + (q0 + mt * 16 + 8) * APADH + nt * 8 + 2 * c) = h1;
            }
        }
        __syncwarp();

        // O += P @ V : P via ldmatrix.x4, V via ldmatrix.x2.trans
#pragma unroll
        for (int s0 = 0; s0 < 64; s0 += 16) {
            unsigned af[2][4];
#pragma unroll
            for (int mt = 0; mt < 2; mt++) {
                unsigned addr = ps_base + (aq_off + (unsigned)(mt * 16 * APADH + s0)) * 2u;
                LDMX4(af[mt][0], af[mt][1], af[mt][2], af[mt][3], addr);
            }
            unsigned row_addr = vs_base + (unsigned)(s0 + (lane & 15)) * (APADH * 2);
#pragma unroll
            for (int dt = 0; dt < 8; dt++) {
                unsigned b0, b1;
                asm volatile(
                    "ldmatrix.sync.aligned.m8n8.x2.trans.shared.b16 {%0,%1}, [%2];"
                    : "=r"(b0), "=r"(b1) : "r"(row_addr + dt * 16));
                unsigned bf[2] = {b0, b1};
                mma_fp16(o[0][dt], af[0], bf);
                mma_fp16(o[1][dt], af[1], bf);
            }
        }
        __syncthreads();
    }

    // epilogue: normalize and store fp16
#pragma unroll
    for (int mt = 0; mt < 2; mt++) {
        float inv0 = 1.0f / lrow[mt][0], inv1 = 1.0f / lrow[mt][1];
#pragma unroll
        for (int dt = 0; dt < 8; dt++) {
            int col = dt * 8 + c * 2;
            __half2 h0 = __floats2half2_rn(o[mt][dt][0] * inv0, o[mt][dt][1] * inv0);
            __half2 h1 = __floats2half2_rn(o[mt][dt][2] * inv1, o[mt][dt][3] * inv1);
            *(__half2*)(Ob + (size_t)(q0 + mt * 16) * D_ + col) = h0;
            *(__half2*)(Ob + (size_t)(q0 + mt * 16 + 8) * D_ + col) = h1;
        }
    }
}

// ---------------------------------------------------------------------------
// Launch. Inputs: x, context, context_mask(int32), wq, bq, wkv, bkv, wp, bp
// ---------------------------------------------------------------------------
extern "C" void kernel_launch(void* const* d_in, const int* in_sizes, int n_in,
                              void* d_out, int out_size)
{
    const float* x = (const float*)d_in[0];
    const float* ctx = (const float*)d_in[1];
    const int* mask = (const int*)d_in[2];
    const float* wq = (const float*)d_in[3];
    const float* bq = (const float*)d_in[4];
    const float* wkv = (const float*)d_in[5];
    const float* bkv = (const float*)d_in[6];
    const float* wp = (const float*)d_in[7];
    const float* bp = (const float*)d_in[8];
    float* out = (float*)d_out;

    __half *Qp, *KVp, *Op;
    cudaGetSymbolAddress((void**)&Qp, g_Qh);
    cudaGetSymbolAddress((void**)&KVp, g_KVh);
    cudaGetSymbolAddress((void**)&Op, g_Oh);

    int gemm_smem = 4 * GTILEH * (int)sizeof(__half);   // 40960
    int attn_smem = ATTN_SMEM_BYTES;                    // ~94KB

    cudaFuncSetAttribute((const void*)gemm_fp16<512, false, true>,
                         cudaFuncAttributeMaxDynamicSharedMemorySize, gemm_smem);
    cudaFuncSetAttribute((const void*)gemm_fp16<512, true, false>,
                         cudaFuncAttributeMaxDynamicSharedMemorySize, gemm_smem);
    cudaFuncSetAttribute((const void*)attn_fp16,
                         cudaFuncAttributeMaxDynamicSharedMemorySize, attn_smem);

    // Q projection: f32 in -> fp16 out
    gemm_fp16<512, false, true><<<dim3(D_ / 128, (B_ * N_) / 128), 256, gemm_smem>>>(
        x, wq, bq, Qp, B_ * N_, D_);
    // KV projection: f32 in -> fp16 out
    gemm_fp16<512, false, true><<<dim3((2 * D_) / 128, (B_ * S_) / 128), 256, gemm_smem>>>(
        ctx, wkv, bkv, KVp, B_ * S_, 2 * D_);
    // attention: fp16 in/out
    attn_fp16<<<dim3(N_ / QT, H_, B_), 256, attn_smem>>>(Qp, KVp, mask, Op);
    // output projection: fp16 in -> f32 out
    gemm_fp16<512, true, false><<<dim3(D_ / 128, (B_ * N_) / 128), 256, gemm_smem>>>(
        Op, wp, bp, out, B_ * N_, D_);
}